// round 2
// baseline (speedup 1.0000x reference)
#include <cuda_runtime.h>
#include <math.h>

#define DIMC   64
#define NV     25
#define TLEN   64
#define NSTEP  3
#define NE     (DIMC * NV)      // 1600 elements per sample state
#define LEAK   0.01f
#define NTHR   256

// ---- shared memory layout (floats) ----
// Wt1[64*64] Wt2[64*64] Wtp[64*64]  (transposed: Wt[c*64+o] = W[o*64+c])
// At[25*25 -> pad 640]              (transposed: At[u*25+v] = A[v*25+u])
// b1[64] b2[64] bp[64]
// pe[(TLEN+NSTEP)*64 = 67*64 = 4288]
// buffers: y, k1, k2, k3, tA, tB   each 1600
#define OFF_WT1  0
#define OFF_WT2  4096
#define OFF_WTP  8192
#define OFF_AT   12288
#define OFF_B1   12928
#define OFF_B2   12992
#define OFF_BP   13056
#define OFF_PE   13120
#define OFF_BUF  17408           // 13120 + 4288
#define SM_FLOATS (OFF_BUF + 6 * NE)      // 27008 floats
#define SM_BYTES  (SM_FLOATS * 4)          // 108032 bytes

__device__ __forceinline__ float lrelu(float x) {
    return x >= 0.0f ? x : LEAK * x;
}

// out[o,v] = act( sum_c Wt[c*64+o] * in[c*25+v] + b[o] )
// thread tile: 4 o's x up-to-2 v's
template<bool ACT>
__device__ __forceinline__ void wmat(const float* Wt, const float* bias,
                                     const float* in, float* out, int tid)
{
    const int vq = tid & 15;
    const int oq = tid >> 4;          // 0..15
    const int o0 = oq * 4;
    const int v1 = vq + 16;
    const bool hv1 = (v1 < NV);

    float a00 = 0.f, a01 = 0.f, a10 = 0.f, a11 = 0.f;
    float a20 = 0.f, a21 = 0.f, a30 = 0.f, a31 = 0.f;

#pragma unroll 8
    for (int c = 0; c < DIMC; c++) {
        const float x0 = in[c * NV + vq];
        const float x1 = hv1 ? in[c * NV + v1] : 0.f;
        const float* wr = Wt + c * 64 + o0;
        const float w0 = wr[0], w1 = wr[1], w2 = wr[2], w3 = wr[3];
        a00 += w0 * x0;  a01 += w0 * x1;
        a10 += w1 * x0;  a11 += w1 * x1;
        a20 += w2 * x0;  a21 += w2 * x1;
        a30 += w3 * x0;  a31 += w3 * x1;
    }

    const float bb0 = bias[o0 + 0], bb1 = bias[o0 + 1];
    const float bb2 = bias[o0 + 2], bb3 = bias[o0 + 3];

    float r00 = a00 + bb0, r10 = a10 + bb1, r20 = a20 + bb2, r30 = a30 + bb3;
    if (ACT) { r00 = lrelu(r00); r10 = lrelu(r10); r20 = lrelu(r20); r30 = lrelu(r30); }
    out[(o0 + 0) * NV + vq] = r00;
    out[(o0 + 1) * NV + vq] = r10;
    out[(o0 + 2) * NV + vq] = r20;
    out[(o0 + 3) * NV + vq] = r30;
    if (hv1) {
        float r01 = a01 + bb0, r11 = a11 + bb1, r21 = a21 + bb2, r31 = a31 + bb3;
        if (ACT) { r01 = lrelu(r01); r11 = lrelu(r11); r21 = lrelu(r21); r31 = lrelu(r31); }
        out[(o0 + 0) * NV + v1] = r01;
        out[(o0 + 1) * NV + v1] = r11;
        out[(o0 + 2) * NV + v1] = r21;
        out[(o0 + 3) * NV + v1] = r31;
    }
}

// out[c,v] = sum_u in[c*25+u] * At[u*25+v]
// thread tile: 4 c's x up-to-2 v's
__device__ __forceinline__ void amat(const float* At, const float* in, float* out, int tid)
{
    const int vq = tid & 15;
    const int cq = tid >> 4;
    const int c0 = cq * 4;
    const int v1 = vq + 16;
    const bool hv1 = (v1 < NV);

    float a00 = 0.f, a01 = 0.f, a10 = 0.f, a11 = 0.f;
    float a20 = 0.f, a21 = 0.f, a30 = 0.f, a31 = 0.f;

#pragma unroll 5
    for (int u = 0; u < NV; u++) {
        const float s0 = At[u * NV + vq];
        const float s1 = hv1 ? At[u * NV + v1] : 0.f;
        const float x0 = in[(c0 + 0) * NV + u];
        const float x1 = in[(c0 + 1) * NV + u];
        const float x2 = in[(c0 + 2) * NV + u];
        const float x3 = in[(c0 + 3) * NV + u];
        a00 += x0 * s0;  a01 += x0 * s1;
        a10 += x1 * s0;  a11 += x1 * s1;
        a20 += x2 * s0;  a21 += x2 * s1;
        a30 += x3 * s0;  a31 += x3 * s1;
    }
    out[(c0 + 0) * NV + vq] = a00;
    out[(c0 + 1) * NV + vq] = a10;
    out[(c0 + 2) * NV + vq] = a20;
    out[(c0 + 3) * NV + vq] = a30;
    if (hv1) {
        out[(c0 + 0) * NV + v1] = a01;
        out[(c0 + 1) * NV + v1] = a11;
        out[(c0 + 2) * NV + v1] = a21;
        out[(c0 + 3) * NV + v1] = a31;
    }
}

// Full ode_func given arg already in tB (pe included). Result -> dst.
__device__ __forceinline__ void ode_eval(const float* At,
                                         const float* Wt1, const float* b1,
                                         const float* Wt2, const float* b2,
                                         const float* Wtp, const float* bp,
                                         float* tA, float* tB, float* dst, int tid)
{
    __syncthreads();                      // tB (arg) ready
    amat(At, tB, tA, tid);  __syncthreads();
    wmat<true>(Wt1, b1, tA, tB, tid);  __syncthreads();
    amat(At, tB, tA, tid);  __syncthreads();
    wmat<true>(Wt2, b2, tA, tB, tid);  __syncthreads();
    wmat<false>(Wtp, bp, tB, dst, tid);  __syncthreads();
}

__global__ void __launch_bounds__(NTHR)
sode_kernel(const float* __restrict__ gfp,   // first_point (B, 64, 25)
            const float* __restrict__ gts,   // time_steps (4)
            const float* __restrict__ gA,    // (25,25)
            const float* __restrict__ gW1, const float* __restrict__ gb1,
            const float* __restrict__ gW2, const float* __restrict__ gb2,
            const float* __restrict__ gWp, const float* __restrict__ gbp,
            const float* __restrict__ gpe,   // (67, 64)
            float* __restrict__ out,         // (4, B, 64, 25)
            int nb)
{
    extern __shared__ float sm[];
    float* Wt1 = sm + OFF_WT1;
    float* Wt2 = sm + OFF_WT2;
    float* Wtp = sm + OFF_WTP;
    float* At  = sm + OFF_AT;
    float* b1  = sm + OFF_B1;
    float* b2  = sm + OFF_B2;
    float* bp  = sm + OFF_BP;
    float* pe  = sm + OFF_PE;
    float* y   = sm + OFF_BUF + 0 * NE;
    float* k1  = sm + OFF_BUF + 1 * NE;
    float* k2  = sm + OFF_BUF + 2 * NE;
    float* k3  = sm + OFF_BUF + 3 * NE;
    float* tA  = sm + OFF_BUF + 4 * NE;
    float* tB  = sm + OFF_BUF + 5 * NE;

    const int tid = threadIdx.x;
    const int n = blockIdx.x;
    const int tt = n & (TLEN - 1);

    // --- cooperative loads of weights (transposed) ---
    for (int i = tid; i < DIMC * DIMC; i += NTHR) {
        const int o = i >> 6, c = i & 63;
        Wt1[c * 64 + o] = gW1[i];
        Wt2[c * 64 + o] = gW2[i];
        Wtp[c * 64 + o] = gWp[i];
    }
    for (int i = tid; i < NV * NV; i += NTHR) {
        const int v = i / NV, u = i % NV;
        At[u * NV + v] = gA[i];
    }
    if (tid < DIMC) { b1[tid] = gb1[tid]; b2[tid] = gb2[tid]; bp[tid] = gbp[tid]; }
    for (int i = tid; i < (TLEN + NSTEP) * DIMC; i += NTHR) pe[i] = gpe[i];

    // --- load state, emit out[0] ---
    const float* fp = gfp + (size_t)n * NE;
    float* out0 = out + (size_t)n * NE;
    for (int e = tid; e < NE; e += NTHR) {
        const float v = fp[e];
        y[e] = v;
        out0[e] = v;
    }
    __syncthreads();

    for (int s = 0; s < NSTEP; s++) {
        const float t0 = gts[s];
        const float dt = gts[s + 1] - gts[s];

        // ---- k1: arg = y ----
        {
            const int ti = (int)floorf(t0);
            const float* per = pe + (ti + tt) * DIMC;
            for (int e = tid; e < NE; e += NTHR)
                tB[e] = y[e] + per[e / NV];
        }
        ode_eval(At, Wt1, b1, Wt2, b2, Wtp, bp, tA, tB, k1, tid);

        // ---- k2: arg = y + dt/3 * k1 ----
        {
            const int ti = (int)floorf(t0 + dt * (1.f / 3.f));
            const float* per = pe + (ti + tt) * DIMC;
            const float f = dt * (1.f / 3.f);
            for (int e = tid; e < NE; e += NTHR)
                tB[e] = y[e] + f * k1[e] + per[e / NV];
        }
        ode_eval(At, Wt1, b1, Wt2, b2, Wtp, bp, tA, tB, k2, tid);

        // ---- k3: arg = y + dt*(k2 - k1/3) ----
        {
            const int ti = (int)floorf(t0 + dt * (2.f / 3.f));
            const float* per = pe + (ti + tt) * DIMC;
            for (int e = tid; e < NE; e += NTHR)
                tB[e] = y[e] + dt * (k2[e] - k1[e] * (1.f / 3.f)) + per[e / NV];
        }
        ode_eval(At, Wt1, b1, Wt2, b2, Wtp, bp, tA, tB, k3, tid);

        // ---- k4: arg = y + dt*(k1 - k2 + k3); fold k2 <- k1 + 3*(k2+k3) ----
        {
            const int ti = (int)floorf(t0 + dt);
            const float* per = pe + (ti + tt) * DIMC;
            for (int e = tid; e < NE; e += NTHR) {
                const float v1 = k1[e], v2 = k2[e], v3 = k3[e];
                tB[e] = y[e] + dt * (v1 - v2 + v3) + per[e / NV];
                k2[e] = v1 + 3.f * (v2 + v3);
            }
        }
        ode_eval(At, Wt1, b1, Wt2, b2, Wtp, bp, tA, tB, k1, tid);  // k4 -> k1

        // ---- y += dt*(acc + k4)/8 ; emit out[s+1] ----
        {
            float* outs = out + (size_t)(s + 1) * nb * NE + (size_t)n * NE;
            const float f = dt * 0.125f;
            for (int e = tid; e < NE; e += NTHR) {
                const float ny = y[e] + f * (k2[e] + k1[e]);
                y[e] = ny;
                outs[e] = ny;
            }
        }
        __syncthreads();
    }
}

extern "C" void kernel_launch(void* const* d_in, const int* in_sizes, int n_in,
                              void* d_out, int out_size)
{
    const float* fp  = (const float*)d_in[0];
    const float* ts  = (const float*)d_in[1];
    const float* A   = (const float*)d_in[2];
    const float* W1  = (const float*)d_in[3];
    const float* b1  = (const float*)d_in[4];
    const float* W2  = (const float*)d_in[5];
    const float* b2  = (const float*)d_in[6];
    const float* Wp  = (const float*)d_in[7];
    const float* bp  = (const float*)d_in[8];
    const float* pe  = (const float*)d_in[9];
    float* out = (float*)d_out;

    const int nb = in_sizes[0] / NE;   // number of samples (16384)

    cudaFuncSetAttribute(sode_kernel,
                         cudaFuncAttributeMaxDynamicSharedMemorySize, SM_BYTES);

    sode_kernel<<<nb, NTHR, SM_BYTES>>>(fp, ts, A, W1, b1, W2, b2, Wp, bp, pe,
                                        out, nb);
}

// round 3
// speedup vs baseline: 1.0442x; 1.0442x over previous
#include <cuda_runtime.h>
#include <math.h>

typedef unsigned long long u64;

#define NV    25
#define NE    1600
#define NTHR  256

// shared float offsets
#define O_WT1 0           // packed-dup W1^T: pair(c,o) at c*128+o*2   (8192 f)
#define O_WT2 8192
#define O_WTP 16384
#define O_AT  24576       // packed-dup A^T:  pair(u,v) at u*64+v*2    (1600 f)
#define O_B1  26176
#define O_B2  26240
#define O_BP  26304
#define O_PE  26368       // 67 x 64                                   (4288 f)
#define O_Y   30656       // state buffers: float2[64][32] = 4096 f each
#define O_K1  34752
#define O_K2  38848
#define O_TA  42944
#define O_TB  47040
#define SMF   51136
#define SMB   (SMF * 4)   // 204544 bytes

extern __shared__ float sm[];

// swizzled pair base (float offset) for state element (row c, col v)
__device__ __forceinline__ int SIX(int c, int v) {
    return c * 64 + ((((v) + (c)) & 31) << 1);
}
__device__ __forceinline__ void fma2(u64& a, u64 x, u64 w) {
    asm("fma.rn.f32x2 %0, %1, %2, %0;" : "+l"(a) : "l"(x), "l"(w));
}
__device__ __forceinline__ float2 unp(u64 a) {
    float2 f; asm("mov.b64 {%0,%1}, %2;" : "=f"(f.x), "=f"(f.y) : "l"(a)); return f;
}

// out[c][v] = sum_u A^T[u][v] * in[c][u]     (tile: 4c x 2v-pairs)
__device__ __forceinline__ void amat(int src, int dst, int tid)
{
    const int vq = tid & 15, c0 = (tid >> 4) << 2;
    u64 acc[4][2];
#pragma unroll
    for (int i = 0; i < 4; i++) { acc[i][0] = 0ULL; acc[i][1] = 0ULL; }
#pragma unroll
    for (int u = 0; u < NV; u++) {
        const float* ar = sm + O_AT + u * 64;
        const u64 a0 = *(const u64*)(ar + vq * 2);
        const u64 a1 = *(const u64*)(ar + vq * 2 + 32);
#pragma unroll
        for (int i = 0; i < 4; i++) {
            const u64 x = *(const u64*)(sm + src + SIX(c0 + i, u));
            fma2(acc[i][0], x, a0);
            fma2(acc[i][1], x, a1);
        }
    }
#pragma unroll
    for (int i = 0; i < 4; i++) {
        *(u64*)(sm + dst + SIX(c0 + i, vq))      = acc[i][0];
        *(u64*)(sm + dst + SIX(c0 + i, vq + 16)) = acc[i][1];
    }
}

// mainloop: acc[i][j] = sum_c W[o0+i][c] * in[c][vq+16j]   (tile: 4o x 2v-pairs)
__device__ __forceinline__ void mmW(int wofs, int src, int tid, u64 acc[4][2])
{
    const int vq = tid & 15, o0 = (tid >> 4) << 2;
#pragma unroll
    for (int i = 0; i < 4; i++) { acc[i][0] = 0ULL; acc[i][1] = 0ULL; }
#pragma unroll 8
    for (int c = 0; c < 64; c++) {
        const u64 x0 = *(const u64*)(sm + src + SIX(c, vq));
        const u64 x1 = *(const u64*)(sm + src + SIX(c, vq + 16));
        const ulonglong2* wv = (const ulonglong2*)(sm + wofs + c * 128 + o0 * 2);
        const ulonglong2 wa = wv[0], wb = wv[1];
        fma2(acc[0][0], x0, wa.x);  fma2(acc[0][1], x1, wa.x);
        fma2(acc[1][0], x0, wa.y);  fma2(acc[1][1], x1, wa.y);
        fma2(acc[2][0], x0, wb.x);  fma2(acc[2][1], x1, wb.x);
        fma2(acc[3][0], x0, wb.y);  fma2(acc[3][1], x1, wb.y);
    }
}

// bias + leaky-relu store into dst
__device__ __forceinline__ void wact(int wofs, int bofs, int src, int dst, int tid)
{
    u64 acc[4][2];
    mmW(wofs, src, tid, acc);
    const int vq = tid & 15, o0 = (tid >> 4) << 2;
#pragma unroll
    for (int i = 0; i < 4; i++) {
        const float b = sm[bofs + o0 + i];
#pragma unroll
        for (int j = 0; j < 2; j++) {
            float2 r = unp(acc[i][j]);
            r.x += b; r.y += b;
            r.x = fmaxf(r.x, 0.01f * r.x);
            r.y = fmaxf(r.y, 0.01f * r.y);
            *(float2*)(sm + dst + SIX(o0 + i, vq + 16 * j)) = r;
        }
    }
}

// core: (A, W1+relu, A, W2+relu), tB -> tB
__device__ __forceinline__ void core(int tid)
{
    __syncthreads();
    amat(O_TB, O_TA, tid);           __syncthreads();
    wact(O_WT1, O_B1, O_TA, O_TB, tid); __syncthreads();
    amat(O_TB, O_TA, tid);           __syncthreads();
    wact(O_WT2, O_B2, O_TA, O_TB, tid); __syncthreads();
}

// tB = y + ca*k1 + cb*k2 + pe(ti)  (per-lane pe rows tt0, tt0+1)
__device__ __forceinline__ void prep(float ca, float cb, int ti, int tt0, int tid)
{
    const int rb = O_PE + (ti + tt0) * 64;
#pragma unroll 1
    for (int e = tid; e < 2048; e += NTHR) {
        const int c = e >> 5, v = e & 31;
        const int sw = SIX(c, v);
        const float2 Y  = *(const float2*)(sm + O_Y  + sw);
        const float2 K1 = *(const float2*)(sm + O_K1 + sw);
        const float2 K2 = *(const float2*)(sm + O_K2 + sw);
        float2 r;
        r.x = Y.x + ca * K1.x + cb * K2.x + sm[rb + c];
        r.y = Y.y + ca * K1.y + cb * K2.y + sm[rb + 64 + c];
        *(float2*)(sm + O_TB + sw) = r;
    }
}

__global__ void __launch_bounds__(NTHR, 1)
sode_kernel(const float* __restrict__ gfp, const float* __restrict__ gts,
            const float* __restrict__ gA,
            const float* __restrict__ gW1, const float* __restrict__ gb1,
            const float* __restrict__ gW2, const float* __restrict__ gb2,
            const float* __restrict__ gWp, const float* __restrict__ gbp,
            const float* __restrict__ gpe,
            float* __restrict__ out, int nb)
{
    const int tid = threadIdx.x;
    const int n0  = blockIdx.x << 1;          // 2 samples per block
    const int tt0 = n0 & 63;

    // weights transposed + pair-duplicated
    for (int i = tid; i < 4096; i += NTHR) {
        const int o = i >> 6, c = i & 63;
        const int d = c * 128 + o * 2;
        float w;
        w = gW1[i]; sm[O_WT1 + d] = w; sm[O_WT1 + d + 1] = w;
        w = gW2[i]; sm[O_WT2 + d] = w; sm[O_WT2 + d + 1] = w;
        w = gWp[i]; sm[O_WTP + d] = w; sm[O_WTP + d + 1] = w;
    }
    // A^T padded to 32 cols, pair-duplicated
    for (int i = tid; i < 800; i += NTHR) {
        const int u = i >> 5, v = i & 31;
        const float a = (v < NV) ? gA[v * NV + u] : 0.f;
        sm[O_AT + u * 64 + v * 2] = a;
        sm[O_AT + u * 64 + v * 2 + 1] = a;
    }
    if (tid < 64) {
        sm[O_B1 + tid] = gb1[tid];
        sm[O_B2 + tid] = gb2[tid];
        sm[O_BP + tid] = gbp[tid];
    }
    for (int i = tid; i < 4288; i += NTHR) sm[O_PE + i] = gpe[i];
    // zero y/k1/k2 (contiguous 12288 floats)
    for (int i = tid; i < 12288; i += NTHR) sm[O_Y + i] = 0.f;
    __syncthreads();

    // load first_point (2 samples), emit out[0]
    for (int e = tid; e < 2 * NE; e += NTHR) {
        const int s = e / NE, r = e - s * NE;
        const int c = r / NV, v = r - c * NV;
        const float val = gfp[(size_t)n0 * NE + e];
        sm[O_Y + SIX(c, v) + s] = val;
        out[(size_t)n0 * NE + e] = val;
    }
    __syncthreads();

    const int vq = tid & 15, o0 = (tid >> 4) << 2;

#pragma unroll 1
    for (int st = 0; st < 3; st++) {
        const float t0 = gts[st];
        const float dt = gts[st + 1] - t0;

        // ---- evals 1 & 2: k1 = f(y), k2 = f(y + dt/3 k1) ----
#pragma unroll 1
        for (int q = 0; q < 2; q++) {
            const float ca = q ? dt * (1.f / 3.f) : 0.f;
            prep(ca, 0.f, (int)floorf(t0 + ca), tt0, tid);
            core(tid);
            u64 acc[4][2];
            mmW(O_WTP, O_TB, tid, acc);
            const int kd = q ? O_K2 : O_K1;
#pragma unroll
            for (int i = 0; i < 4; i++) {
                const float b = sm[O_BP + o0 + i];
#pragma unroll
                for (int j = 0; j < 2; j++) {
                    float2 r = unp(acc[i][j]);
                    r.x += b; r.y += b;
                    *(float2*)(sm + kd + SIX(o0 + i, vq + 16 * j)) = r;
                }
            }
            __syncthreads();
        }

        // ---- eval 3: k3 = f(y + dt*(k2 - k1/3)), fused epilogue:
        //      tB <- k4 arg (incl pe),  k2 <- k1 + 3*(k2+k3) ----
        prep(-dt * (1.f / 3.f), dt, (int)floorf(t0 + dt * (2.f / 3.f)), tt0, tid);
        core(tid);
        {
            u64 acc[4][2];
            mmW(O_WTP, O_TB, tid, acc);
            __syncthreads();               // everyone done reading tB
            const int rb = O_PE + ((int)floorf(t0 + dt) + tt0) * 64;
#pragma unroll
            for (int i = 0; i < 4; i++) {
                const int o = o0 + i;
                const float b = sm[O_BP + o];
                const float p0 = sm[rb + o], p1 = sm[rb + 64 + o];
#pragma unroll
                for (int j = 0; j < 2; j++) {
                    const int sw = SIX(o, vq + 16 * j);
                    float2 k3 = unp(acc[i][j]);
                    k3.x += b; k3.y += b;
                    const float2 K1 = *(const float2*)(sm + O_K1 + sw);
                    const float2 K2 = *(const float2*)(sm + O_K2 + sw);
                    const float2 Y  = *(const float2*)(sm + O_Y  + sw);
                    float2 tb, k2n;
                    tb.x = Y.x + dt * (K1.x - K2.x + k3.x) + p0;
                    tb.y = Y.y + dt * (K1.y - K2.y + k3.y) + p1;
                    k2n.x = K1.x + 3.f * (K2.x + k3.x);
                    k2n.y = K1.y + 3.f * (K2.y + k3.y);
                    *(float2*)(sm + O_TB + sw) = tb;
                    *(float2*)(sm + O_K2 + sw) = k2n;
                }
            }
            __syncthreads();
        }

        // ---- eval 4: k4 = f(tB); y += dt/8*(k2acc + k4); emit out ----
        core(tid);
        {
            u64 acc[4][2];
            mmW(O_WTP, O_TB, tid, acc);
            __syncthreads();
            float* ob = out + (size_t)(st + 1) * nb * NE + (size_t)n0 * NE;
            const float f = dt * 0.125f;
#pragma unroll
            for (int i = 0; i < 4; i++) {
                const int o = o0 + i;
                const float b = sm[O_BP + o];
#pragma unroll
                for (int j = 0; j < 2; j++) {
                    const int v = vq + 16 * j;
                    const int sw = SIX(o, v);
                    float2 k4 = unp(acc[i][j]);
                    k4.x += b; k4.y += b;
                    const float2 K2 = *(const float2*)(sm + O_K2 + sw);
                    float2 Y = *(const float2*)(sm + O_Y + sw);
                    Y.x += f * (K2.x + k4.x);
                    Y.y += f * (K2.y + k4.y);
                    *(float2*)(sm + O_Y + sw) = Y;
                    if (v < NV) {
                        ob[o * NV + v]      = Y.x;
                        ob[NE + o * NV + v] = Y.y;
                    }
                }
            }
            __syncthreads();
        }
    }
}

extern "C" void kernel_launch(void* const* d_in, const int* in_sizes, int n_in,
                              void* d_out, int out_size)
{
    const float* fp = (const float*)d_in[0];
    const float* ts = (const float*)d_in[1];
    const float* A  = (const float*)d_in[2];
    const float* W1 = (const float*)d_in[3];
    const float* b1 = (const float*)d_in[4];
    const float* W2 = (const float*)d_in[5];
    const float* b2 = (const float*)d_in[6];
    const float* Wp = (const float*)d_in[7];
    const float* bp = (const float*)d_in[8];
    const float* pe = (const float*)d_in[9];
    float* out = (float*)d_out;

    const int nb = in_sizes[0] / NE;

    cudaFuncSetAttribute(sode_kernel,
                         cudaFuncAttributeMaxDynamicSharedMemorySize, SMB);
    sode_kernel<<<nb / 2, NTHR, SMB>>>(fp, ts, A, W1, b1, W2, b2, Wp, bp, pe,
                                       out, nb);
}

// round 4
// speedup vs baseline: 1.0792x; 1.0335x over previous
#include <cuda_runtime.h>
#include <math.h>

typedef unsigned long long u64;

#define NV   25
#define NE   1600
#define NTHR 128

// shared memory float offsets
#define O_WT1 0          // Wt[c*64+o] = W[o*64+c]        (4096)
#define O_WT2 4096
#define O_WTP 8192
#define O_AT  12288      // A^T pair-dup: [u*64 + v*2]    (1600)
#define O_B1  13888
#define O_B2  13952
#define O_BP  14016
#define O_PE  14080      // 7 rows x 64                   (448)
#define O_Y   14528      // state: 64 rows x 64 u64-cols  (8192 f each)
#define O_K1  22720
#define O_K2  30912
#define O_TA  39104
#define O_TB  47296
#define SMF   55488
#define SMB   (SMF * 4)  // 221952 bytes

extern __shared__ float sm[];

// swizzled float offset of u64 element (row c, col j), j = sp*32 + v
__device__ __forceinline__ int SIX(int c, int j) {
    return c * 128 + (((j + c) & 63) << 1);
}
__device__ __forceinline__ u64 pack2(float x) {
    u64 r; asm("mov.b64 %0,{%1,%1};" : "=l"(r) : "f"(x)); return r;
}
__device__ __forceinline__ void fma2(u64& a, u64 x, u64 w) {
    asm("fma.rn.f32x2 %0,%1,%2,%0;" : "+l"(a) : "l"(x), "l"(w));
}
__device__ __forceinline__ float2 unp(u64 a) {
    float2 f; asm("mov.b64 {%0,%1},%2;" : "=f"(f.x), "=f"(f.y) : "l"(a)); return f;
}

// W mainloop: acc[i][k] = sum_c W[o0+i][c] * x[c][vq+16k]
__device__ __forceinline__ void mmW(int wofs, int src, int vq, int o0, u64 acc[8][4])
{
#pragma unroll
    for (int i = 0; i < 8; i++)
#pragma unroll
        for (int k = 0; k < 4; k++) acc[i][k] = 0ULL;
#pragma unroll 4
    for (int c = 0; c < 64; c++) {
        const u64 x0 = *(const u64*)(sm + src + SIX(c, vq));
        const u64 x1 = *(const u64*)(sm + src + SIX(c, vq + 16));
        const u64 x2 = *(const u64*)(sm + src + SIX(c, vq + 32));
        const u64 x3 = *(const u64*)(sm + src + SIX(c, vq + 48));
        const float4 wa = *(const float4*)(sm + wofs + c * 64 + o0);
        const float4 wb = *(const float4*)(sm + wofs + c * 64 + o0 + 4);
        const float wv[8] = {wa.x, wa.y, wa.z, wa.w, wb.x, wb.y, wb.z, wb.w};
#pragma unroll
        for (int i = 0; i < 8; i++) {
            const u64 wp = pack2(wv[i]);
            fma2(acc[i][0], x0, wp);
            fma2(acc[i][1], x1, wp);
            fma2(acc[i][2], x2, wp);
            fma2(acc[i][3], x3, wp);
        }
    }
}

// A matmul: dst[c][sp*32+v] = sum_u At[u][v] * src[c][sp*32+u]
__device__ __forceinline__ void amat(int src, int dst, int cq, int vg)
{
    u64 acc[4][2][4];
#pragma unroll
    for (int ci = 0; ci < 4; ci++)
#pragma unroll
        for (int sp = 0; sp < 2; sp++)
#pragma unroll
            for (int m = 0; m < 4; m++) acc[ci][sp][m] = 0ULL;
#pragma unroll 5
    for (int u = 0; u < NV; u++) {
        const u64 a0 = *(const u64*)(sm + O_AT + u * 64 + vg * 2);
        const u64 a1 = *(const u64*)(sm + O_AT + u * 64 + (vg + 8) * 2);
        const u64 a2 = *(const u64*)(sm + O_AT + u * 64 + (vg + 16) * 2);
        const u64 a3 = *(const u64*)(sm + O_AT + u * 64 + (vg + 24) * 2);
#pragma unroll
        for (int ci = 0; ci < 4; ci++) {
            const int c = cq + 16 * ci;
#pragma unroll
            for (int sp = 0; sp < 2; sp++) {
                const u64 x = *(const u64*)(sm + src + SIX(c, sp * 32 + u));
                fma2(acc[ci][sp][0], x, a0);
                fma2(acc[ci][sp][1], x, a1);
                fma2(acc[ci][sp][2], x, a2);
                fma2(acc[ci][sp][3], x, a3);
            }
        }
    }
#pragma unroll
    for (int ci = 0; ci < 4; ci++) {
        const int c = cq + 16 * ci;
#pragma unroll
        for (int sp = 0; sp < 2; sp++)
#pragma unroll
            for (int m = 0; m < 4; m++)
                *(u64*)(sm + dst + SIX(c, sp * 32 + vg + 8 * m)) = acc[ci][sp][m];
    }
}

// W stage with bias + leaky relu, TA -> TB
__device__ __forceinline__ void wact(int wofs, int bofs, int vq, int o0)
{
    u64 acc[8][4];
    mmW(wofs, O_TA, vq, o0, acc);
#pragma unroll
    for (int i = 0; i < 8; i++) {
        const float b = sm[bofs + o0 + i];
#pragma unroll
        for (int k = 0; k < 4; k++) {
            float2 r = unp(acc[i][k]);
            r.x += b; r.y += b;
            r.x = fmaxf(r.x, 0.01f * r.x);
            r.y = fmaxf(r.y, 0.01f * r.y);
            *(float2*)(sm + O_TB + SIX(o0 + i, vq + 16 * k)) = r;
        }
    }
}

// (A, W1+relu, A, W2+relu): TB -> TB
__device__ __forceinline__ void core(int cq, int vg, int vq, int o0)
{
    amat(O_TB, O_TA, cq, vg);  __syncthreads();
    wact(O_WT1, O_B1, vq, o0); __syncthreads();
    amat(O_TB, O_TA, cq, vg);  __syncthreads();
    wact(O_WT2, O_B2, vq, o0); __syncthreads();
}

__global__ void __launch_bounds__(NTHR, 1)
sode_kernel(const float* __restrict__ gfp, const float* __restrict__ gts,
            const float* __restrict__ gA,
            const float* __restrict__ gW1, const float* __restrict__ gb1,
            const float* __restrict__ gW2, const float* __restrict__ gb2,
            const float* __restrict__ gWp, const float* __restrict__ gbp,
            const float* __restrict__ gpe,
            float* __restrict__ out, int nb)
{
    const int tid = threadIdx.x;
    const int n0  = blockIdx.x << 2;      // 4 samples per block
    const int tt0 = n0 & 63;
    const int vq  = tid & 15, o0 = (tid >> 4) << 3;
    const int cq  = tid & 15, vg = tid >> 4;

    // Wt[c*64+o] = W[o*64+c]  (strided gmem reads, conflict-free STS)
    for (int i = tid; i < 4096; i += NTHR) {
        const int c = i >> 6, o = i & 63;
        sm[O_WT1 + i] = gW1[o * 64 + c];
        sm[O_WT2 + i] = gW2[o * 64 + c];
        sm[O_WTP + i] = gWp[o * 64 + c];
    }
    // A^T padded to 32 cols, pair-duplicated
    for (int i = tid; i < 800; i += NTHR) {
        const int u = i >> 5, v = i & 31;
        const float a = (v < NV) ? gA[v * NV + u] : 0.f;
        sm[O_AT + u * 64 + v * 2]     = a;
        sm[O_AT + u * 64 + v * 2 + 1] = a;
    }
    if (tid < 64) {
        sm[O_B1 + tid] = gb1[tid];
        sm[O_B2 + tid] = gb2[tid];
        sm[O_BP + tid] = gbp[tid];
    }
    for (int i = tid; i < 448; i += NTHR) sm[O_PE + i] = gpe[tt0 * 64 + i];
    // zero Y,K1,K2 (contiguous 24576 floats)
    {
        const float4 z = make_float4(0.f, 0.f, 0.f, 0.f);
        for (int i = tid; i < 6144; i += NTHR)
            ((float4*)(sm + O_Y))[i] = z;
    }
    __syncthreads();

    // load first_point (4 samples), emit out[0]
    for (int e = tid; e < 4 * NE; e += NTHR) {
        const int s = e / NE, r = e - s * NE;
        const int c = r / NV, v = r - c * NV;
        const float val = gfp[(size_t)n0 * NE + e];
        sm[O_Y + SIX(c, (s >> 1) * 32 + v) + (s & 1)] = val;
        out[(size_t)n0 * NE + e] = val;
    }
    __syncthreads();

#pragma unroll 1
    for (int st = 0; st < 3; st++) {
        const float t0 = gts[st];
        const float dt = gts[st + 1] - t0;
        const int ti1 = (int)floorf(t0);
        const int ti2 = (int)floorf(t0 + dt * (1.f / 3.f));
        const int ti3 = (int)floorf(t0 + dt * (2.f / 3.f));
        const int ti4 = (int)floorf(t0 + dt);

        // prep1: TB = Y + pe(ti1)
#pragma unroll 1
        for (int e = tid; e < 4096; e += NTHR) {
            const int c = e >> 6, jr = e & 63;
            const int sp = ((jr - c) & 63) >> 5;
            float2 Yv = *(const float2*)(sm + O_Y + c * 128 + jr * 2);
            Yv.x += sm[O_PE + (ti1 + 2 * sp) * 64 + c];
            Yv.y += sm[O_PE + (ti1 + 2 * sp + 1) * 64 + c];
            *(float2*)(sm + O_TB + c * 128 + jr * 2) = Yv;
        }
        __syncthreads();

        // ---- eval 1: k1; fused: TB <- y + dt/3*k1 + pe(ti2) ----
        core(cq, vg, vq, o0);
        {
            u64 acc[8][4];
            mmW(O_WTP, O_TB, vq, o0, acc);
            __syncthreads();
            const float f = dt * (1.f / 3.f);
#pragma unroll
            for (int i = 0; i < 8; i++) {
                const int o = o0 + i;
                const float b = sm[O_BP + o];
#pragma unroll
                for (int k = 0; k < 4; k++) {
                    const int sp = k >> 1;
                    const int sw = SIX(o, vq + 16 * k);
                    float2 k1 = unp(acc[i][k]);
                    k1.x += b; k1.y += b;
                    *(float2*)(sm + O_K1 + sw) = k1;
                    const float2 Yv = *(const float2*)(sm + O_Y + sw);
                    float2 tb;
                    tb.x = Yv.x + f * k1.x + sm[O_PE + (ti2 + 2 * sp) * 64 + o];
                    tb.y = Yv.y + f * k1.y + sm[O_PE + (ti2 + 2 * sp + 1) * 64 + o];
                    *(float2*)(sm + O_TB + sw) = tb;
                }
            }
            __syncthreads();
        }

        // ---- eval 2: k2; fused: TB <- y + dt*(k2 - k1/3) + pe(ti3) ----
        core(cq, vg, vq, o0);
        {
            u64 acc[8][4];
            mmW(O_WTP, O_TB, vq, o0, acc);
            __syncthreads();
            const float f3 = dt * (1.f / 3.f);
#pragma unroll
            for (int i = 0; i < 8; i++) {
                const int o = o0 + i;
                const float b = sm[O_BP + o];
#pragma unroll
                for (int k = 0; k < 4; k++) {
                    const int sp = k >> 1;
                    const int sw = SIX(o, vq + 16 * k);
                    float2 k2 = unp(acc[i][k]);
                    k2.x += b; k2.y += b;
                    *(float2*)(sm + O_K2 + sw) = k2;
                    const float2 K1 = *(const float2*)(sm + O_K1 + sw);
                    const float2 Yv = *(const float2*)(sm + O_Y + sw);
                    float2 tb;
                    tb.x = Yv.x + dt * k2.x - f3 * K1.x + sm[O_PE + (ti3 + 2 * sp) * 64 + o];
                    tb.y = Yv.y + dt * k2.y - f3 * K1.y + sm[O_PE + (ti3 + 2 * sp + 1) * 64 + o];
                    *(float2*)(sm + O_TB + sw) = tb;
                }
            }
            __syncthreads();
        }

        // ---- eval 3: k3; fused: TB <- y + dt*(k1-k2+k3) + pe(ti4);
        //      K2 <- k1 + 3*(k2 + k3) ----
        core(cq, vg, vq, o0);
        {
            u64 acc[8][4];
            mmW(O_WTP, O_TB, vq, o0, acc);
            __syncthreads();
#pragma unroll
            for (int i = 0; i < 8; i++) {
                const int o = o0 + i;
                const float b = sm[O_BP + o];
#pragma unroll
                for (int k = 0; k < 4; k++) {
                    const int sp = k >> 1;
                    const int sw = SIX(o, vq + 16 * k);
                    float2 k3 = unp(acc[i][k]);
                    k3.x += b; k3.y += b;
                    const float2 K1 = *(const float2*)(sm + O_K1 + sw);
                    const float2 K2 = *(const float2*)(sm + O_K2 + sw);
                    const float2 Yv = *(const float2*)(sm + O_Y + sw);
                    float2 tb, kn;
                    tb.x = Yv.x + dt * (K1.x - K2.x + k3.x) + sm[O_PE + (ti4 + 2 * sp) * 64 + o];
                    tb.y = Yv.y + dt * (K1.y - K2.y + k3.y) + sm[O_PE + (ti4 + 2 * sp + 1) * 64 + o];
                    kn.x = K1.x + 3.f * (K2.x + k3.x);
                    kn.y = K1.y + 3.f * (K2.y + k3.y);
                    *(float2*)(sm + O_TB + sw) = tb;
                    *(float2*)(sm + O_K2 + sw) = kn;
                }
            }
            __syncthreads();
        }

        // ---- eval 4: k4; y += dt/8*(K2 + k4); emit out[st+1] ----
        core(cq, vg, vq, o0);
        {
            u64 acc[8][4];
            mmW(O_WTP, O_TB, vq, o0, acc);
            float* ob = out + (size_t)(st + 1) * nb * NE + (size_t)n0 * NE;
            const float f = dt * 0.125f;
#pragma unroll
            for (int i = 0; i < 8; i++) {
                const int o = o0 + i;
                const float b = sm[O_BP + o];
#pragma unroll
                for (int k = 0; k < 4; k++) {
                    const int sp = k >> 1;
                    const int v = vq + 16 * (k & 1);
                    const int sw = SIX(o, vq + 16 * k);
                    float2 k4 = unp(acc[i][k]);
                    k4.x += b; k4.y += b;
                    const float2 K2 = *(const float2*)(sm + O_K2 + sw);
                    float2 Yv = *(const float2*)(sm + O_Y + sw);
                    Yv.x += f * (K2.x + k4.x);
                    Yv.y += f * (K2.y + k4.y);
                    *(float2*)(sm + O_Y + sw) = Yv;
                    if (v < NV) {
                        ob[(size_t)(2 * sp) * NE + o * NV + v]     = Yv.x;
                        ob[(size_t)(2 * sp + 1) * NE + o * NV + v] = Yv.y;
                    }
                }
            }
            __syncthreads();
        }
    }
}

extern "C" void kernel_launch(void* const* d_in, const int* in_sizes, int n_in,
                              void* d_out, int out_size)
{
    const float* fp = (const float*)d_in[0];
    const float* ts = (const float*)d_in[1];
    const float* A  = (const float*)d_in[2];
    const float* W1 = (const float*)d_in[3];
    const float* b1 = (const float*)d_in[4];
    const float* W2 = (const float*)d_in[5];
    const float* b2 = (const float*)d_in[6];
    const float* Wp = (const float*)d_in[7];
    const float* bp = (const float*)d_in[8];
    const float* pe = (const float*)d_in[9];
    float* out = (float*)d_out;

    const int nb = in_sizes[0] / NE;

    cudaFuncSetAttribute(sode_kernel,
                         cudaFuncAttributeMaxDynamicSharedMemorySize, SMB);
    sode_kernel<<<nb / 4, NTHR, SMB>>>(fp, ts, A, W1, b1, W2, b2, Wp, bp, pe,
                                       out, nb);
}

// round 5
// speedup vs baseline: 1.4402x; 1.3346x over previous
#include <cuda_runtime.h>
#include <math.h>

typedef unsigned long long u64;

#define NV   25
#define NE   1600
#define NTHR 256

// shared memory float offsets
#define O_WT1 0          // Wt[c*64+o] = W[o*64+c]        (4096)
#define O_WT2 4096
#define O_WTP 8192
#define O_AT  12288      // A^T pair-dup: [u*64 + v*2]    (1600)
#define O_B1  13888
#define O_B2  13952
#define O_BP  14016
#define O_PE  14080      // 7 rows x 64                   (448)
#define O_Y   14528      // state: 64 rows x 64 u64-cols  (8192 f each)
#define O_K1  22720
#define O_K2  30912
#define O_TA  39104
#define O_TB  47296
#define SMF   55488
#define SMB   (SMF * 4)  // 221952 bytes

extern __shared__ float sm[];

// swizzled float offset of u64 element (row c, col j), j = sp*32 + v
__device__ __forceinline__ int SIX(int c, int j) {
    return c * 128 + (((j + c) & 63) << 1);
}
__device__ __forceinline__ u64 pack2(float x) {
    u64 r; asm("mov.b64 %0,{%1,%1};" : "=l"(r) : "f"(x)); return r;
}
__device__ __forceinline__ void fma2(u64& a, u64 x, u64 w) {
    asm("fma.rn.f32x2 %0,%1,%2,%0;" : "+l"(a) : "l"(x), "l"(w));
}
__device__ __forceinline__ float2 unp(u64 a) {
    float2 f; asm("mov.b64 {%0,%1},%2;" : "=f"(f.x), "=f"(f.y) : "l"(a)); return f;
}

// W mainloop: acc[i][k] = sum_c W[o0+i][c] * x[c][vq+16k]
// 256 threads: vq = tid&15, o0 = (tid>>4)*4  (16 o-groups x 4 rows)
__device__ __forceinline__ void mmW(int wofs, int src, int vq, int o0, u64 acc[4][4])
{
#pragma unroll
    for (int i = 0; i < 4; i++)
#pragma unroll
        for (int k = 0; k < 4; k++) acc[i][k] = 0ULL;
#pragma unroll 8
    for (int c = 0; c < 64; c++) {
        const u64 x0 = *(const u64*)(sm + src + SIX(c, vq));
        const u64 x1 = *(const u64*)(sm + src + SIX(c, vq + 16));
        const u64 x2 = *(const u64*)(sm + src + SIX(c, vq + 32));
        const u64 x3 = *(const u64*)(sm + src + SIX(c, vq + 48));
        const float4 wa = *(const float4*)(sm + wofs + c * 64 + o0);
        const float wv[4] = {wa.x, wa.y, wa.z, wa.w};
#pragma unroll
        for (int i = 0; i < 4; i++) {
            const u64 wp = pack2(wv[i]);
            fma2(acc[i][0], x0, wp);
            fma2(acc[i][1], x1, wp);
            fma2(acc[i][2], x2, wp);
            fma2(acc[i][3], x3, wp);
        }
    }
}

// A matmul: dst[c][sp*32+v] = sum_u At[u][v] * src[c][sp*32+u]
// 256 threads: cq = tid&31 (c in {cq, cq+32}), vg = tid>>5 (v = vg+8m)
__device__ __forceinline__ void amat(int src, int dst, int cq, int vg)
{
    u64 acc[2][2][4];
#pragma unroll
    for (int ci = 0; ci < 2; ci++)
#pragma unroll
        for (int sp = 0; sp < 2; sp++)
#pragma unroll
            for (int m = 0; m < 4; m++) acc[ci][sp][m] = 0ULL;
#pragma unroll 5
    for (int u = 0; u < NV; u++) {
        const u64 a0 = *(const u64*)(sm + O_AT + u * 64 + vg * 2);
        const u64 a1 = *(const u64*)(sm + O_AT + u * 64 + (vg + 8) * 2);
        const u64 a2 = *(const u64*)(sm + O_AT + u * 64 + (vg + 16) * 2);
        const u64 a3 = *(const u64*)(sm + O_AT + u * 64 + (vg + 24) * 2);
#pragma unroll
        for (int ci = 0; ci < 2; ci++) {
            const int c = cq + 32 * ci;
#pragma unroll
            for (int sp = 0; sp < 2; sp++) {
                const u64 x = *(const u64*)(sm + src + SIX(c, sp * 32 + u));
                fma2(acc[ci][sp][0], x, a0);
                fma2(acc[ci][sp][1], x, a1);
                fma2(acc[ci][sp][2], x, a2);
                fma2(acc[ci][sp][3], x, a3);
            }
        }
    }
#pragma unroll
    for (int ci = 0; ci < 2; ci++) {
        const int c = cq + 32 * ci;
#pragma unroll
        for (int sp = 0; sp < 2; sp++)
#pragma unroll
            for (int m = 0; m < 4; m++)
                *(u64*)(sm + dst + SIX(c, sp * 32 + vg + 8 * m)) = acc[ci][sp][m];
    }
}

// W stage with bias + leaky relu, TA -> TB
__device__ __forceinline__ void wact(int wofs, int bofs, int vq, int o0)
{
    u64 acc[4][4];
    mmW(wofs, O_TA, vq, o0, acc);
#pragma unroll
    for (int i = 0; i < 4; i++) {
        const float b = sm[bofs + o0 + i];
#pragma unroll
        for (int k = 0; k < 4; k++) {
            float2 r = unp(acc[i][k]);
            r.x += b; r.y += b;
            r.x = fmaxf(r.x, 0.01f * r.x);
            r.y = fmaxf(r.y, 0.01f * r.y);
            *(float2*)(sm + O_TB + SIX(o0 + i, vq + 16 * k)) = r;
        }
    }
}

// (A, W1+relu, A, W2+relu): TB -> TB
__device__ __forceinline__ void core(int cq, int vg, int vq, int o0)
{
    amat(O_TB, O_TA, cq, vg);  __syncthreads();
    wact(O_WT1, O_B1, vq, o0); __syncthreads();
    amat(O_TB, O_TA, cq, vg);  __syncthreads();
    wact(O_WT2, O_B2, vq, o0); __syncthreads();
}

__global__ void __launch_bounds__(NTHR, 1)
sode_kernel(const float* __restrict__ gfp, const float* __restrict__ gts,
            const float* __restrict__ gA,
            const float* __restrict__ gW1, const float* __restrict__ gb1,
            const float* __restrict__ gW2, const float* __restrict__ gb2,
            const float* __restrict__ gWp, const float* __restrict__ gbp,
            const float* __restrict__ gpe,
            float* __restrict__ out, int nb)
{
    const int tid = threadIdx.x;
    const int n0  = blockIdx.x << 2;      // 4 samples per block
    const int tt0 = n0 & 63;
    const int vq  = tid & 15, o0 = (tid >> 4) << 2;
    const int cq  = tid & 31, vg = tid >> 5;

    // Wt[c*64+o] = W[o*64+c]
    for (int i = tid; i < 4096; i += NTHR) {
        const int c = i >> 6, o = i & 63;
        sm[O_WT1 + i] = gW1[o * 64 + c];
        sm[O_WT2 + i] = gW2[o * 64 + c];
        sm[O_WTP + i] = gWp[o * 64 + c];
    }
    // A^T padded to 32 cols, pair-duplicated
    for (int i = tid; i < 800; i += NTHR) {
        const int u = i >> 5, v = i & 31;
        const float a = (v < NV) ? gA[v * NV + u] : 0.f;
        sm[O_AT + u * 64 + v * 2]     = a;
        sm[O_AT + u * 64 + v * 2 + 1] = a;
    }
    if (tid < 64) {
        sm[O_B1 + tid] = gb1[tid];
        sm[O_B2 + tid] = gb2[tid];
        sm[O_BP + tid] = gbp[tid];
    }
    for (int i = tid; i < 448; i += NTHR) sm[O_PE + i] = gpe[tt0 * 64 + i];
    // zero Y,K1,K2 (contiguous 24576 floats)
    {
        const float4 z = make_float4(0.f, 0.f, 0.f, 0.f);
        for (int i = tid; i < 6144; i += NTHR)
            ((float4*)(sm + O_Y))[i] = z;
    }
    __syncthreads();

    // load first_point (4 samples), emit out[0]
    for (int e = tid; e < 4 * NE; e += NTHR) {
        const int s = e / NE, r = e - s * NE;
        const int c = r / NV, v = r - c * NV;
        const float val = gfp[(size_t)n0 * NE + e];
        sm[O_Y + SIX(c, (s >> 1) * 32 + v) + (s & 1)] = val;
        out[(size_t)n0 * NE + e] = val;
    }
    __syncthreads();

#pragma unroll 1
    for (int st = 0; st < 3; st++) {
        const float t0 = gts[st];
        const float dt = gts[st + 1] - t0;
        const int ti1 = (int)floorf(t0);
        const int ti2 = (int)floorf(t0 + dt * (1.f / 3.f));
        const int ti3 = (int)floorf(t0 + dt * (2.f / 3.f));
        const int ti4 = (int)floorf(t0 + dt);

        // prep1: TB = Y + pe(ti1)
#pragma unroll 1
        for (int e = tid; e < 4096; e += NTHR) {
            const int c = e >> 6, jr = e & 63;
            const int sp = ((jr - c) & 63) >> 5;
            float2 Yv = *(const float2*)(sm + O_Y + c * 128 + jr * 2);
            Yv.x += sm[O_PE + (ti1 + 2 * sp) * 64 + c];
            Yv.y += sm[O_PE + (ti1 + 2 * sp + 1) * 64 + c];
            *(float2*)(sm + O_TB + c * 128 + jr * 2) = Yv;
        }
        __syncthreads();

        // ---- eval 1: k1; fused: TB <- y + dt/3*k1 + pe(ti2) ----
        core(cq, vg, vq, o0);
        {
            u64 acc[4][4];
            mmW(O_WTP, O_TB, vq, o0, acc);
            __syncthreads();
            const float f = dt * (1.f / 3.f);
#pragma unroll
            for (int i = 0; i < 4; i++) {
                const int o = o0 + i;
                const float b = sm[O_BP + o];
#pragma unroll
                for (int k = 0; k < 4; k++) {
                    const int sp = k >> 1;
                    const int sw = SIX(o, vq + 16 * k);
                    float2 k1 = unp(acc[i][k]);
                    k1.x += b; k1.y += b;
                    *(float2*)(sm + O_K1 + sw) = k1;
                    const float2 Yv = *(const float2*)(sm + O_Y + sw);
                    float2 tb;
                    tb.x = Yv.x + f * k1.x + sm[O_PE + (ti2 + 2 * sp) * 64 + o];
                    tb.y = Yv.y + f * k1.y + sm[O_PE + (ti2 + 2 * sp + 1) * 64 + o];
                    *(float2*)(sm + O_TB + sw) = tb;
                }
            }
            __syncthreads();
        }

        // ---- eval 2: k2; fused: TB <- y + dt*(k2 - k1/3) + pe(ti3) ----
        core(cq, vg, vq, o0);
        {
            u64 acc[4][4];
            mmW(O_WTP, O_TB, vq, o0, acc);
            __syncthreads();
            const float f3 = dt * (1.f / 3.f);
#pragma unroll
            for (int i = 0; i < 4; i++) {
                const int o = o0 + i;
                const float b = sm[O_BP + o];
#pragma unroll
                for (int k = 0; k < 4; k++) {
                    const int sp = k >> 1;
                    const int sw = SIX(o, vq + 16 * k);
                    float2 k2 = unp(acc[i][k]);
                    k2.x += b; k2.y += b;
                    *(float2*)(sm + O_K2 + sw) = k2;
                    const float2 K1 = *(const float2*)(sm + O_K1 + sw);
                    const float2 Yv = *(const float2*)(sm + O_Y + sw);
                    float2 tb;
                    tb.x = Yv.x + dt * k2.x - f3 * K1.x + sm[O_PE + (ti3 + 2 * sp) * 64 + o];
                    tb.y = Yv.y + dt * k2.y - f3 * K1.y + sm[O_PE + (ti3 + 2 * sp + 1) * 64 + o];
                    *(float2*)(sm + O_TB + sw) = tb;
                }
            }
            __syncthreads();
        }

        // ---- eval 3: k3; fused: TB <- y + dt*(k1-k2+k3) + pe(ti4);
        //      K2 <- k1 + 3*(k2 + k3) ----
        core(cq, vg, vq, o0);
        {
            u64 acc[4][4];
            mmW(O_WTP, O_TB, vq, o0, acc);
            __syncthreads();
#pragma unroll
            for (int i = 0; i < 4; i++) {
                const int o = o0 + i;
                const float b = sm[O_BP + o];
#pragma unroll
                for (int k = 0; k < 4; k++) {
                    const int sp = k >> 1;
                    const int sw = SIX(o, vq + 16 * k);
                    float2 k3 = unp(acc[i][k]);
                    k3.x += b; k3.y += b;
                    const float2 K1 = *(const float2*)(sm + O_K1 + sw);
                    const float2 K2 = *(const float2*)(sm + O_K2 + sw);
                    const float2 Yv = *(const float2*)(sm + O_Y + sw);
                    float2 tb, kn;
                    tb.x = Yv.x + dt * (K1.x - K2.x + k3.x) + sm[O_PE + (ti4 + 2 * sp) * 64 + o];
                    tb.y = Yv.y + dt * (K1.y - K2.y + k3.y) + sm[O_PE + (ti4 + 2 * sp + 1) * 64 + o];
                    kn.x = K1.x + 3.f * (K2.x + k3.x);
                    kn.y = K1.y + 3.f * (K2.y + k3.y);
                    *(float2*)(sm + O_TB + sw) = tb;
                    *(float2*)(sm + O_K2 + sw) = kn;
                }
            }
            __syncthreads();
        }

        // ---- eval 4: k4; y += dt/8*(K2 + k4); emit out[st+1] ----
        core(cq, vg, vq, o0);
        {
            u64 acc[4][4];
            mmW(O_WTP, O_TB, vq, o0, acc);
            float* ob = out + (size_t)(st + 1) * nb * NE + (size_t)n0 * NE;
            const float f = dt * 0.125f;
#pragma unroll
            for (int i = 0; i < 4; i++) {
                const int o = o0 + i;
                const float b = sm[O_BP + o];
#pragma unroll
                for (int k = 0; k < 4; k++) {
                    const int sp = k >> 1;
                    const int v = vq + 16 * (k & 1);
                    const int sw = SIX(o, vq + 16 * k);
                    float2 k4 = unp(acc[i][k]);
                    k4.x += b; k4.y += b;
                    const float2 K2 = *(const float2*)(sm + O_K2 + sw);
                    float2 Yv = *(const float2*)(sm + O_Y + sw);
                    Yv.x += f * (K2.x + k4.x);
                    Yv.y += f * (K2.y + k4.y);
                    *(float2*)(sm + O_Y + sw) = Yv;
                    if (v < NV) {
                        ob[(size_t)(2 * sp) * NE + o * NV + v]     = Yv.x;
                        ob[(size_t)(2 * sp + 1) * NE + o * NV + v] = Yv.y;
                    }
                }
            }
            __syncthreads();
        }
    }
}

extern "C" void kernel_launch(void* const* d_in, const int* in_sizes, int n_in,
                              void* d_out, int out_size)
{
    const float* fp = (const float*)d_in[0];
    const float* ts = (const float*)d_in[1];
    const float* A  = (const float*)d_in[2];
    const float* W1 = (const float*)d_in[3];
    const float* b1 = (const float*)d_in[4];
    const float* W2 = (const float*)d_in[5];
    const float* b2 = (const float*)d_in[6];
    const float* Wp = (const float*)d_in[7];
    const float* bp = (const float*)d_in[8];
    const float* pe = (const float*)d_in[9];
    float* out = (float*)d_out;

    const int nb = in_sizes[0] / NE;

    cudaFuncSetAttribute(sode_kernel,
                         cudaFuncAttributeMaxDynamicSharedMemorySize, SMB);
    sode_kernel<<<nb / 4, NTHR, SMB>>>(fp, ts, A, W1, b1, W2, b2, Wp, bp, pe,
                                       out, nb);
}

// round 6
// speedup vs baseline: 1.5243x; 1.0584x over previous
#include <cuda_runtime.h>
#include <math.h>

typedef unsigned long long u64;

#define NV   25
#define NE   1600
#define NTHR 256
#define RS   66              // floats per state row = 33 u64 (pad kills conflicts)

// shared float offsets
#define O_WT1 0              // Wt[c*64+o] = W[o*64+c]           (4096)
#define O_WT2 4096
#define O_WTP 8192
#define O_AT  12288          // A^T pair-dup: [u*64 + v*2]       (1600)
#define O_B1  13888
#define O_B2  13952
#define O_BP  14016
#define O_PE  14080          // 5 rows x 64                      (320)
#define O_Y   14400          // 64 rows x RS floats              (4224 each)
#define O_TA  (O_Y  + 64 * RS)
#define O_TB  (O_TA + 64 * RS)
#define SMF   (O_TB + 64 * RS)       // 27072 floats
#define SMB   (SMF * 4)              // 108288 bytes -> 2 blocks/SM

extern __shared__ float sm[];

__device__ __forceinline__ u64 pack2(float x) {
    u64 r; asm("mov.b64 %0,{%1,%1};" : "=l"(r) : "f"(x)); return r;
}
__device__ __forceinline__ void fma2(u64& a, u64 x, u64 w) {
    asm("fma.rn.f32x2 %0,%1,%2,%0;" : "+l"(a) : "l"(x), "l"(w));
}
__device__ __forceinline__ float2 unp(u64 a) {
    float2 f; asm("mov.b64 {%0,%1},%2;" : "=f"(f.x), "=f"(f.y) : "l"(a)); return f;
}

// W mainloop: acc[i][k] = sum_c W[o0+i][c] * x[c][vq+16k]   (4o x 2 j-pairs)
__device__ __forceinline__ void mmW(int wofs, int src, int vq, int o0, u64 acc[4][2])
{
#pragma unroll
    for (int i = 0; i < 4; i++) { acc[i][0] = 0ULL; acc[i][1] = 0ULL; }
#pragma unroll 8
    for (int c = 0; c < 64; c++) {
        const u64 x0 = *(const u64*)(sm + src + c * RS + vq * 2);
        const u64 x1 = *(const u64*)(sm + src + c * RS + vq * 2 + 32);
        const float4 wa = *(const float4*)(sm + wofs + c * 64 + o0);
        const float wv[4] = {wa.x, wa.y, wa.z, wa.w};
#pragma unroll
        for (int i = 0; i < 4; i++) {
            const u64 wp = pack2(wv[i]);
            fma2(acc[i][0], x0, wp);
            fma2(acc[i][1], x1, wp);
        }
    }
}

// A matmul: dst[c][v] = sum_u At[u][v] * src[c][u]   (2c x 4v)
__device__ __forceinline__ void amat(int src, int dst, int cq, int vg)
{
    u64 acc[2][4];
#pragma unroll
    for (int ci = 0; ci < 2; ci++)
#pragma unroll
        for (int m = 0; m < 4; m++) acc[ci][m] = 0ULL;
#pragma unroll 5
    for (int u = 0; u < NV; u++) {
        const float* ar = sm + O_AT + u * 64;
        const u64 a0 = *(const u64*)(ar + vg * 2);
        const u64 a1 = *(const u64*)(ar + vg * 2 + 16);
        const u64 a2 = *(const u64*)(ar + vg * 2 + 32);
        const u64 a3 = *(const u64*)(ar + vg * 2 + 48);
#pragma unroll
        for (int ci = 0; ci < 2; ci++) {
            const u64 x = *(const u64*)(sm + src + (cq + 32 * ci) * RS + u * 2);
            fma2(acc[ci][0], x, a0);
            fma2(acc[ci][1], x, a1);
            fma2(acc[ci][2], x, a2);
            fma2(acc[ci][3], x, a3);
        }
    }
#pragma unroll
    for (int ci = 0; ci < 2; ci++) {
        float* dr = sm + dst + (cq + 32 * ci) * RS + vg * 2;
        *(u64*)(dr)      = acc[ci][0];
        *(u64*)(dr + 16) = acc[ci][1];
        *(u64*)(dr + 32) = acc[ci][2];
        *(u64*)(dr + 48) = acc[ci][3];
    }
}

// W stage with bias + leaky relu, TA -> TB
__device__ __forceinline__ void wact(int wofs, int bofs, int vq, int o0)
{
    u64 acc[4][2];
    mmW(wofs, O_TA, vq, o0, acc);
#pragma unroll
    for (int i = 0; i < 4; i++) {
        const float b = sm[bofs + o0 + i];
        float* dr = sm + O_TB + (o0 + i) * RS + vq * 2;
#pragma unroll
        for (int k = 0; k < 2; k++) {
            float2 r = unp(acc[i][k]);
            r.x += b; r.y += b;
            r.x = fmaxf(r.x, 0.01f * r.x);
            r.y = fmaxf(r.y, 0.01f * r.y);
            *(float2*)(dr + 32 * k) = r;
        }
    }
}

// (A, W1+relu, A, W2+relu): TB -> TB
__device__ __forceinline__ void core(int cq, int vg, int vq, int o0)
{
    amat(O_TB, O_TA, cq, vg);  __syncthreads();
    wact(O_WT1, O_B1, vq, o0); __syncthreads();
    amat(O_TB, O_TA, cq, vg);  __syncthreads();
    wact(O_WT2, O_B2, vq, o0); __syncthreads();
}

__global__ void __launch_bounds__(NTHR, 2)
sode_kernel(const float* __restrict__ gfp, const float* __restrict__ gts,
            const float* __restrict__ gA,
            const float* __restrict__ gW1, const float* __restrict__ gb1,
            const float* __restrict__ gW2, const float* __restrict__ gb2,
            const float* __restrict__ gWp, const float* __restrict__ gbp,
            const float* __restrict__ gpe,
            float* __restrict__ out, int nb)
{
    const int tid = threadIdx.x;
    const int n0  = blockIdx.x << 1;       // 2 samples per block
    const int tt0 = n0 & 63;
    const int vq  = tid & 15, o0 = (tid >> 4) << 2;
    const int cq  = tid & 31, vg = tid >> 5;

    // Wt[c*64+o] = W[o*64+c] (strided gmem reads, linear STS)
    for (int i = tid; i < 4096; i += NTHR) {
        const int c = i >> 6, o = i & 63;
        sm[O_WT1 + i] = gW1[o * 64 + c];
        sm[O_WT2 + i] = gW2[o * 64 + c];
        sm[O_WTP + i] = gWp[o * 64 + c];
    }
    // A^T padded to 32 cols, pair-duplicated
    for (int i = tid; i < 800; i += NTHR) {
        const int u = i >> 5, v = i & 31;
        const float a = (v < NV) ? gA[v * NV + u] : 0.f;
        sm[O_AT + u * 64 + v * 2]     = a;
        sm[O_AT + u * 64 + v * 2 + 1] = a;
    }
    if (tid < 64) {
        sm[O_B1 + tid] = gb1[tid];
        sm[O_B2 + tid] = gb2[tid];
        sm[O_BP + tid] = gbp[tid];
    }
    for (int i = tid; i < 320; i += NTHR) sm[O_PE + i] = gpe[tt0 * 64 + i];
    // zero Y (pads must stay finite)
    for (int i = tid; i < 64 * RS; i += NTHR) sm[O_Y + i] = 0.f;
    __syncthreads();

    // load first_point (2 samples), emit out[0]
    for (int e = tid; e < 2 * NE; e += NTHR) {
        const int s = e / NE, r = e - s * NE;
        const int c = r / NV, v = r - c * NV;
        const float val = gfp[(size_t)n0 * NE + e];
        sm[O_Y + c * RS + v * 2 + s] = val;
        out[(size_t)n0 * NE + e] = val;
    }
    __syncthreads();

    float2 k1[4][2], k2[4][2];

#pragma unroll 1
    for (int st = 0; st < 3; st++) {
        const float t0 = gts[st];
        const float dt = gts[st + 1] - t0;
        // relative PE row indices (absolute tt0 already folded into O_PE load)
        const int ti1 = (int)floorf(t0) - st;                      // relative base
        const int ti2 = (int)floorf(t0 + dt * (1.f / 3.f)) - st;
        const int ti3 = (int)floorf(t0 + dt * (2.f / 3.f)) - st;
        const int ti4 = (int)floorf(t0 + dt) - st;
        // NOTE: PE rows loaded are absolute tt0..tt0+4; relative row for
        // (ti, sample s) = (ti_abs - 0) + s where ti_abs in [0,4].
        const int r1 = ti1 + st, r2 = ti2 + st, r3 = ti3 + st, r4 = ti4 + st;

        // prep1: TB = Y + pe(r1)   (per-thread tile)
#pragma unroll
        for (int i = 0; i < 4; i++) {
            const int o = o0 + i;
            const float px = sm[O_PE + r1 * 64 + o];
            const float py = sm[O_PE + (r1 + 1) * 64 + o];
            const float* yr = sm + O_Y + o * RS + vq * 2;
            float* tr = sm + O_TB + o * RS + vq * 2;
#pragma unroll
            for (int k = 0; k < 2; k++) {
                float2 Yv = *(const float2*)(yr + 32 * k);
                Yv.x += px; Yv.y += py;
                *(float2*)(tr + 32 * k) = Yv;
            }
        }
        __syncthreads();

        // ---- eval 1: k1 (regs); TB <- y + dt/3*k1 + pe(r2) ----
        core(cq, vg, vq, o0);
        {
            u64 acc[4][2];
            mmW(O_WTP, O_TB, vq, o0, acc);
            __syncthreads();
            const float f = dt * (1.f / 3.f);
#pragma unroll
            for (int i = 0; i < 4; i++) {
                const int o = o0 + i;
                const float b = sm[O_BP + o];
                const float px = sm[O_PE + r2 * 64 + o];
                const float py = sm[O_PE + (r2 + 1) * 64 + o];
                const float* yr = sm + O_Y + o * RS + vq * 2;
                float* tr = sm + O_TB + o * RS + vq * 2;
#pragma unroll
                for (int k = 0; k < 2; k++) {
                    float2 v = unp(acc[i][k]);
                    v.x += b; v.y += b;
                    k1[i][k] = v;
                    const float2 Yv = *(const float2*)(yr + 32 * k);
                    float2 tb;
                    tb.x = Yv.x + f * v.x + px;
                    tb.y = Yv.y + f * v.y + py;
                    *(float2*)(tr + 32 * k) = tb;
                }
            }
            __syncthreads();
        }

        // ---- eval 2: k2 (regs); TB <- y + dt*k2 - dt/3*k1 + pe(r3) ----
        core(cq, vg, vq, o0);
        {
            u64 acc[4][2];
            mmW(O_WTP, O_TB, vq, o0, acc);
            __syncthreads();
            const float f3 = dt * (1.f / 3.f);
#pragma unroll
            for (int i = 0; i < 4; i++) {
                const int o = o0 + i;
                const float b = sm[O_BP + o];
                const float px = sm[O_PE + r3 * 64 + o];
                const float py = sm[O_PE + (r3 + 1) * 64 + o];
                const float* yr = sm + O_Y + o * RS + vq * 2;
                float* tr = sm + O_TB + o * RS + vq * 2;
#pragma unroll
                for (int k = 0; k < 2; k++) {
                    float2 v = unp(acc[i][k]);
                    v.x += b; v.y += b;
                    k2[i][k] = v;
                    const float2 Yv = *(const float2*)(yr + 32 * k);
                    float2 tb;
                    tb.x = Yv.x + dt * v.x - f3 * k1[i][k].x + px;
                    tb.y = Yv.y + dt * v.y - f3 * k1[i][k].y + py;
                    *(float2*)(tr + 32 * k) = tb;
                }
            }
            __syncthreads();
        }

        // ---- eval 3: k3; TB <- y + dt*(k1-k2+k3) + pe(r4);
        //      k2 <- k1 + 3*(k2+k3) ----
        core(cq, vg, vq, o0);
        {
            u64 acc[4][2];
            mmW(O_WTP, O_TB, vq, o0, acc);
            __syncthreads();
#pragma unroll
            for (int i = 0; i < 4; i++) {
                const int o = o0 + i;
                const float b = sm[O_BP + o];
                const float px = sm[O_PE + r4 * 64 + o];
                const float py = sm[O_PE + (r4 + 1) * 64 + o];
                const float* yr = sm + O_Y + o * RS + vq * 2;
                float* tr = sm + O_TB + o * RS + vq * 2;
#pragma unroll
                for (int k = 0; k < 2; k++) {
                    float2 k3 = unp(acc[i][k]);
                    k3.x += b; k3.y += b;
                    const float2 K1 = k1[i][k], K2 = k2[i][k];
                    const float2 Yv = *(const float2*)(yr + 32 * k);
                    float2 tb, kn;
                    tb.x = Yv.x + dt * (K1.x - K2.x + k3.x) + px;
                    tb.y = Yv.y + dt * (K1.y - K2.y + k3.y) + py;
                    kn.x = K1.x + 3.f * (K2.x + k3.x);
                    kn.y = K1.y + 3.f * (K2.y + k3.y);
                    k2[i][k] = kn;
                    *(float2*)(tr + 32 * k) = tb;
                }
            }
            __syncthreads();
        }

        // ---- eval 4: k4; y += dt/8*(k2 + k4); emit out[st+1] ----
        core(cq, vg, vq, o0);
        {
            u64 acc[4][2];
            mmW(O_WTP, O_TB, vq, o0, acc);
            __syncthreads();
            float* ob = out + (size_t)(st + 1) * nb * NE + (size_t)n0 * NE;
            const float f = dt * 0.125f;
#pragma unroll
            for (int i = 0; i < 4; i++) {
                const int o = o0 + i;
                const float b = sm[O_BP + o];
                float* yr = sm + O_Y + o * RS + vq * 2;
#pragma unroll
                for (int k = 0; k < 2; k++) {
                    const int v = vq + 16 * k;
                    float2 k4 = unp(acc[i][k]);
                    k4.x += b; k4.y += b;
                    const float2 K2 = k2[i][k];
                    float2 Yv = *(const float2*)(yr + 32 * k);
                    Yv.x += f * (K2.x + k4.x);
                    Yv.y += f * (K2.y + k4.y);
                    *(float2*)(yr + 32 * k) = Yv;
                    if (v < NV) {
                        ob[o * NV + v]      = Yv.x;
                        ob[NE + o * NV + v] = Yv.y;
                    }
                }
            }
            __syncthreads();
        }
    }
}

extern "C" void kernel_launch(void* const* d_in, const int* in_sizes, int n_in,
                              void* d_out, int out_size)
{
    const float* fp = (const float*)d_in[0];
    const float* ts = (const float*)d_in[1];
    const float* A  = (const float*)d_in[2];
    const float* W1 = (const float*)d_in[3];
    const float* b1 = (const float*)d_in[4];
    const float* W2 = (const float*)d_in[5];
    const float* b2 = (const float*)d_in[6];
    const float* Wp = (const float*)d_in[7];
    const float* bp = (const float*)d_in[8];
    const float* pe = (const float*)d_in[9];
    float* out = (float*)d_out;

    const int nb = in_sizes[0] / NE;

    cudaFuncSetAttribute(sode_kernel,
                         cudaFuncAttributeMaxDynamicSharedMemorySize, SMB);
    sode_kernel<<<nb / 2, NTHR, SMB>>>(fp, ts, A, W1, b1, W2, b2, Wp, bp, pe,
                                       out, nb);
}

// round 7
// speedup vs baseline: 1.9045x; 1.2495x over previous
#include <cuda_runtime.h>
#include <math.h>

typedef unsigned long long u64;

#define NV   25
#define NE   1600
#define NTHR 128
#define RSF  66               // floats per state row (33 u64, odd -> 2-wf columns)

// shared float offsets
#define O_WT1 0               // Wt[c*64+o] = W[o*64+c]       (4096)
#define O_WT2 4096
#define O_WTP 8192
#define O_AT  12288           // scalar A^T: [u*32 + v], pad  (800)
#define O_B1  13088
#define O_B2  13152
#define O_BP  13216
#define O_PE  13280           // 5 rows x 64                  (320)
#define O_Y   13600           // 64 x RSF floats              (4224 each)
#define O_TA  (O_Y  + 64 * RSF)
#define O_TB  (O_TA + 64 * RSF)
#define SMF   (O_TB + 64 * RSF)     // 26272 floats
#define SMB   (SMF * 4)             // 105088 bytes -> 2 blocks/SM

extern __shared__ float sm[];

__device__ __forceinline__ u64 pack2(float x) {
    u64 r; asm("mov.b64 %0,{%1,%1};" : "=l"(r) : "f"(x)); return r;
}
__device__ __forceinline__ void fma2(u64& a, u64 x, u64 w) {
    asm("fma.rn.f32x2 %0,%1,%2,%0;" : "+l"(a) : "l"(x), "l"(w));
}
__device__ __forceinline__ float2 unp(u64 a) {
    float2 f; asm("mov.b64 {%0,%1},%2;" : "=f"(f.x), "=f"(f.y) : "l"(a)); return f;
}

// W mainloop: acc[i][k] = sum_c W[o0+i][c] * x[c][jq+16k]
// 8 o-rows per thread; halves of a warp share jq -> x loads broadcast-dedup.
__device__ __forceinline__ void mmW(int wofs, int src, int jq, int o0, u64 acc[8][2])
{
#pragma unroll
    for (int i = 0; i < 8; i++) { acc[i][0] = 0ULL; acc[i][1] = 0ULL; }
#pragma unroll 8
    for (int c = 0; c < 64; c++) {
        const float* xr = sm + src + c * RSF + jq * 2;
        const u64 x0 = *(const u64*)(xr);
        const u64 x1 = *(const u64*)(xr + 32);
        const float4 wa = *(const float4*)(sm + wofs + c * 64 + o0);
        const float4 wb = *(const float4*)(sm + wofs + c * 64 + o0 + 4);
        const float wv[8] = {wa.x, wa.y, wa.z, wa.w, wb.x, wb.y, wb.z, wb.w};
#pragma unroll
        for (int i = 0; i < 8; i++) {
            const u64 wp = pack2(wv[i]);
            fma2(acc[i][0], x0, wp);
            fma2(acc[i][1], x1, wp);
        }
    }
}

// A matmul: dst[c][v] = sum_u At[u][v] * src[c][u]
// thread: c in {cq, cq+32}, v in [vb, vb+8)
__device__ __forceinline__ void amat(int src, int dst, int cq, int vb)
{
    u64 acc[2][8];
#pragma unroll
    for (int ci = 0; ci < 2; ci++)
#pragma unroll
        for (int m = 0; m < 8; m++) acc[ci][m] = 0ULL;
#pragma unroll 5
    for (int u = 0; u < NV; u++) {
        const u64 x0 = *(const u64*)(sm + src + cq * RSF + u * 2);
        const u64 x1 = *(const u64*)(sm + src + (cq + 32) * RSF + u * 2);
        const float4 aa = *(const float4*)(sm + O_AT + u * 32 + vb);
        const float4 ab = *(const float4*)(sm + O_AT + u * 32 + vb + 4);
        const float av[8] = {aa.x, aa.y, aa.z, aa.w, ab.x, ab.y, ab.z, ab.w};
#pragma unroll
        for (int m = 0; m < 8; m++) {
            const u64 ap = pack2(av[m]);
            fma2(acc[0][m], x0, ap);
            fma2(acc[1][m], x1, ap);
        }
    }
#pragma unroll
    for (int ci = 0; ci < 2; ci++) {
        float* dr = sm + dst + (cq + 32 * ci) * RSF + vb * 2;
#pragma unroll
        for (int m = 0; m < 8; m++)
            *(u64*)(dr + m * 2) = acc[ci][m];
    }
}

// W stage with bias + leaky relu, TA -> TB
__device__ __forceinline__ void wact(int wofs, int bofs, int jq, int o0)
{
    u64 acc[8][2];
    mmW(wofs, O_TA, jq, o0, acc);
#pragma unroll
    for (int i = 0; i < 8; i++) {
        const float b = sm[bofs + o0 + i];
        float* dr = sm + O_TB + (o0 + i) * RSF + jq * 2;
#pragma unroll
        for (int k = 0; k < 2; k++) {
            float2 r = unp(acc[i][k]);
            r.x += b; r.y += b;
            r.x = fmaxf(r.x, 0.01f * r.x);
            r.y = fmaxf(r.y, 0.01f * r.y);
            *(float2*)(dr + 32 * k) = r;
        }
    }
}

// (A, W1+relu, A, W2+relu): TB -> TB
__device__ __forceinline__ void core(int cq, int vb, int jq, int o0)
{
    amat(O_TB, O_TA, cq, vb);  __syncthreads();
    wact(O_WT1, O_B1, jq, o0); __syncthreads();
    amat(O_TB, O_TA, cq, vb);  __syncthreads();
    wact(O_WT2, O_B2, jq, o0); __syncthreads();
}

__global__ void __launch_bounds__(NTHR, 2)
sode_kernel(const float* __restrict__ gfp, const float* __restrict__ gts,
            const float* __restrict__ gA,
            const float* __restrict__ gW1, const float* __restrict__ gb1,
            const float* __restrict__ gW2, const float* __restrict__ gb2,
            const float* __restrict__ gWp, const float* __restrict__ gbp,
            const float* __restrict__ gpe,
            float* __restrict__ out, int nb)
{
    const int tid = threadIdx.x;
    const int n0  = blockIdx.x << 1;        // 2 samples per block
    const int tt0 = n0 & 63;
    const int jq  = tid & 15, o0 = (tid >> 4) << 3;
    const int cq  = tid & 31, vb = (tid >> 5) << 3;

    // Wt[c*64+o] = W[o*64+c]
    for (int i = tid; i < 4096; i += NTHR) {
        const int c = i >> 6, o = i & 63;
        sm[O_WT1 + i] = gW1[o * 64 + c];
        sm[O_WT2 + i] = gW2[o * 64 + c];
        sm[O_WTP + i] = gWp[o * 64 + c];
    }
    // scalar A^T padded to 32 cols
    for (int i = tid; i < 800; i += NTHR) {
        const int u = i >> 5, v = i & 31;
        sm[O_AT + i] = (v < NV) ? gA[v * NV + u] : 0.f;
    }
    if (tid < 64) {
        sm[O_B1 + tid] = gb1[tid];
        sm[O_B2 + tid] = gb2[tid];
        sm[O_BP + tid] = gbp[tid];
    }
    for (int i = tid; i < 320; i += NTHR) sm[O_PE + i] = gpe[tt0 * 64 + i];
    // zero Y (pads must stay finite)
    for (int i = tid; i < 64 * RSF; i += NTHR) sm[O_Y + i] = 0.f;
    __syncthreads();

    // load first_point (2 samples), emit out[0]
    for (int e = tid; e < 2 * NE; e += NTHR) {
        const int s = e / NE, r = e - s * NE;
        const int c = r / NV, v = r - c * NV;
        const float val = gfp[(size_t)n0 * NE + e];
        sm[O_Y + c * RSF + v * 2 + s] = val;
        out[(size_t)n0 * NE + e] = val;
    }
    __syncthreads();

    float2 k1[8][2], k2[8][2];

#pragma unroll 1
    for (int st = 0; st < 3; st++) {
        const float t0 = gts[st];
        const float dt = gts[st + 1] - t0;
        const int r1 = (int)floorf(t0);
        const int r2 = (int)floorf(t0 + dt * (1.f / 3.f));
        const int r3 = (int)floorf(t0 + dt * (2.f / 3.f));
        const int r4 = (int)floorf(t0 + dt);

        // prep1: TB = Y + pe(r1)
#pragma unroll
        for (int i = 0; i < 8; i++) {
            const int o = o0 + i;
            const float px = sm[O_PE + r1 * 64 + o];
            const float py = sm[O_PE + (r1 + 1) * 64 + o];
            const float* yr = sm + O_Y + o * RSF + jq * 2;
            float* tr = sm + O_TB + o * RSF + jq * 2;
#pragma unroll
            for (int k = 0; k < 2; k++) {
                float2 Yv = *(const float2*)(yr + 32 * k);
                Yv.x += px; Yv.y += py;
                *(float2*)(tr + 32 * k) = Yv;
            }
        }
        __syncthreads();

        // ---- eval 1: k1 (regs); TB <- y + dt/3*k1 + pe(r2) ----
        core(cq, vb, jq, o0);
        {
            u64 acc[8][2];
            mmW(O_WTP, O_TB, jq, o0, acc);
            __syncthreads();
            const float f = dt * (1.f / 3.f);
#pragma unroll
            for (int i = 0; i < 8; i++) {
                const int o = o0 + i;
                const float b = sm[O_BP + o];
                const float px = sm[O_PE + r2 * 64 + o];
                const float py = sm[O_PE + (r2 + 1) * 64 + o];
                const float* yr = sm + O_Y + o * RSF + jq * 2;
                float* tr = sm + O_TB + o * RSF + jq * 2;
#pragma unroll
                for (int k = 0; k < 2; k++) {
                    float2 v = unp(acc[i][k]);
                    v.x += b; v.y += b;
                    k1[i][k] = v;
                    const float2 Yv = *(const float2*)(yr + 32 * k);
                    float2 tb;
                    tb.x = Yv.x + f * v.x + px;
                    tb.y = Yv.y + f * v.y + py;
                    *(float2*)(tr + 32 * k) = tb;
                }
            }
            __syncthreads();
        }

        // ---- eval 2: k2 (regs); TB <- y + dt*k2 - dt/3*k1 + pe(r3) ----
        core(cq, vb, jq, o0);
        {
            u64 acc[8][2];
            mmW(O_WTP, O_TB, jq, o0, acc);
            __syncthreads();
            const float f3 = dt * (1.f / 3.f);
#pragma unroll
            for (int i = 0; i < 8; i++) {
                const int o = o0 + i;
                const float b = sm[O_BP + o];
                const float px = sm[O_PE + r3 * 64 + o];
                const float py = sm[O_PE + (r3 + 1) * 64 + o];
                const float* yr = sm + O_Y + o * RSF + jq * 2;
                float* tr = sm + O_TB + o * RSF + jq * 2;
#pragma unroll
                for (int k = 0; k < 2; k++) {
                    float2 v = unp(acc[i][k]);
                    v.x += b; v.y += b;
                    k2[i][k] = v;
                    const float2 Yv = *(const float2*)(yr + 32 * k);
                    float2 tb;
                    tb.x = Yv.x + dt * v.x - f3 * k1[i][k].x + px;
                    tb.y = Yv.y + dt * v.y - f3 * k1[i][k].y + py;
                    *(float2*)(tr + 32 * k) = tb;
                }
            }
            __syncthreads();
        }

        // ---- eval 3: k3; TB <- y + dt*(k1-k2+k3) + pe(r4);
        //      k2 <- k1 + 3*(k2+k3) ----
        core(cq, vb, jq, o0);
        {
            u64 acc[8][2];
            mmW(O_WTP, O_TB, jq, o0, acc);
            __syncthreads();
#pragma unroll
            for (int i = 0; i < 8; i++) {
                const int o = o0 + i;
                const float b = sm[O_BP + o];
                const float px = sm[O_PE + r4 * 64 + o];
                const float py = sm[O_PE + (r4 + 1) * 64 + o];
                const float* yr = sm + O_Y + o * RSF + jq * 2;
                float* tr = sm + O_TB + o * RSF + jq * 2;
#pragma unroll
                for (int k = 0; k < 2; k++) {
                    float2 k3 = unp(acc[i][k]);
                    k3.x += b; k3.y += b;
                    const float2 K1 = k1[i][k], K2 = k2[i][k];
                    const float2 Yv = *(const float2*)(yr + 32 * k);
                    float2 tb, kn;
                    tb.x = Yv.x + dt * (K1.x - K2.x + k3.x) + px;
                    tb.y = Yv.y + dt * (K1.y - K2.y + k3.y) + py;
                    kn.x = K1.x + 3.f * (K2.x + k3.x);
                    kn.y = K1.y + 3.f * (K2.y + k3.y);
                    k2[i][k] = kn;
                    *(float2*)(tr + 32 * k) = tb;
                }
            }
            __syncthreads();
        }

        // ---- eval 4: k4; y += dt/8*(k2 + k4); emit out[st+1] ----
        core(cq, vb, jq, o0);
        {
            u64 acc[8][2];
            mmW(O_WTP, O_TB, jq, o0, acc);
            __syncthreads();
            float* ob = out + (size_t)(st + 1) * nb * NE + (size_t)n0 * NE;
            const float f = dt * 0.125f;
#pragma unroll
            for (int i = 0; i < 8; i++) {
                const int o = o0 + i;
                const float b = sm[O_BP + o];
                float* yr = sm + O_Y + o * RSF + jq * 2;
#pragma unroll
                for (int k = 0; k < 2; k++) {
                    const int v = jq + 16 * k;
                    float2 k4 = unp(acc[i][k]);
                    k4.x += b; k4.y += b;
                    const float2 K2 = k2[i][k];
                    float2 Yv = *(const float2*)(yr + 32 * k);
                    Yv.x += f * (K2.x + k4.x);
                    Yv.y += f * (K2.y + k4.y);
                    *(float2*)(yr + 32 * k) = Yv;
                    if (v < NV) {
                        ob[o * NV + v]      = Yv.x;
                        ob[NE + o * NV + v] = Yv.y;
                    }
                }
            }
            __syncthreads();
        }
    }
}

extern "C" void kernel_launch(void* const* d_in, const int* in_sizes, int n_in,
                              void* d_out, int out_size)
{
    const float* fp = (const float*)d_in[0];
    const float* ts = (const float*)d_in[1];
    const float* A  = (const float*)d_in[2];
    const float* W1 = (const float*)d_in[3];
    const float* b1 = (const float*)d_in[4];
    const float* W2 = (const float*)d_in[5];
    const float* b2 = (const float*)d_in[6];
    const float* Wp = (const float*)d_in[7];
    const float* bp = (const float*)d_in[8];
    const float* pe = (const float*)d_in[9];
    float* out = (float*)d_out;

    const int nb = in_sizes[0] / NE;

    cudaFuncSetAttribute(sode_kernel,
                         cudaFuncAttributeMaxDynamicSharedMemorySize, SMB);
    sode_kernel<<<nb / 2, NTHR, SMB>>>(fp, ts, A, W1, b1, W2, b2, Wp, bp, pe,
                                       out, nb);
}